// round 9
// baseline (speedup 1.0000x reference)
#include <cuda_runtime.h>

// ---------------------------------------------------------------------------
// WT_series_decomp: 4-level lowpass DWT analysis+synthesis, season = x - trend.
// 2 CTAs per row (left/right half, halo recompute), 512 thr, 4 CTAs/SM.
// Block-contiguous tiling: 4 outputs/thread (analysis), 8 outputs/thread
// (synthesis) -> 7 LDS.64 + STS.128 per quad, 4 LDS.64 + 2 STS.128 per octave.
//
// Right-half slice bases: lo1:8134 lo2:4070 lo3:2038 lo4:1022
//                         t1:2044  t2:4092  t3:8188  out:16384
// All stage block-counts identical across halves; only offsets differ.
// ---------------------------------------------------------------------------

#define NT      512
#define N0      32768
#define NROWS   512
#define HALF    16777216

#define P1_ALLOC (8 + 8264)     // front zeros + data extent 8262
#define P2_ALLOC (8 + 4136)     // front zeros + data extent 4134
#define SMEM_FLOATS (P1_ALLOC + P2_ALLOC)   // 12416
#define SMEM_BYTES  (SMEM_FLOATS * 4)       // 49664 -> 4 CTAs/SM

// DEC_LO
#define G0 (-0.010597401784997278f)
#define G1 ( 0.032883011666982945f)
#define G2 ( 0.030841381835986965f)
#define G3 (-0.18703481171888114f)
#define G4 (-0.02798376941698385f)
#define G5 ( 0.6308807679295904f)
#define G6 ( 0.7148465705525415f)
#define G7 ( 0.23037781330885523f)
// H[k] = DEC_LO[7-k]
#define H0 G7
#define H1 G6
#define H2 G5
#define H3 G4
#define H4 G3
#define H5 G2
#define H6 G1
#define H7 G0

__device__ __forceinline__ float dot8(float2 a, float2 b, float2 c, float2 d) {
    float s = a.x * H0;
    s = fmaf(a.y, H1, s);
    s = fmaf(b.x, H2, s);
    s = fmaf(b.y, H3, s);
    s = fmaf(c.x, H4, s);
    s = fmaf(c.y, H5, s);
    s = fmaf(d.x, H6, s);
    s = fmaf(d.y, H7, s);
    return s;
}

// Stage-1 analysis from GLOBAL x. Quad i -> outputs global og0=ob+4i..+3,
// reads x[2*og0-6 .. 2*og0+7]. Fast for i in [i_lo, i_hi); guarded otherwise
// (clamped x loads; outputs og >= 16387 forced to 0 = zero-extension).
__device__ __forceinline__ void afb_gq(const float* __restrict__ x,
                                       float* __restrict__ out,
                                       int ob, int i_lo, int i_hi, int tid) {
    for (int i = tid; i < 2064; i += NT) {
        int og0 = ob + 4 * i;
        float4 r;
        if (i >= i_lo && i < i_hi) {
            const float2* pp = (const float2*)(x + 2 * og0 - 6);
            float2 v0 = pp[0], v1 = pp[1], v2 = pp[2], v3 = pp[3];
            float2 v4 = pp[4], v5 = pp[5], v6 = pp[6];
            r.x = dot8(v0, v1, v2, v3);
            r.y = dot8(v1, v2, v3, v4);
            r.z = dot8(v2, v3, v4, v5);
            r.w = dot8(v3, v4, v5, v6);
        } else {
            const float Ht[8] = {H0, H1, H2, H3, H4, H5, H6, H7};
            float rr[4];
#pragma unroll
            for (int k = 0; k < 4; ++k) {
                int og = og0 + k;
                float s = 0.0f;
                if (og < 16387) {
#pragma unroll
                    for (int j = 0; j < 8; ++j) {
                        int ix = 2 * og - 6 + j;
                        float v = (ix >= 0 && ix < N0) ? x[ix] : 0.0f;
                        s = fmaf(v, Ht[j], s);
                    }
                }
                rr[k] = s;
            }
            r = make_float4(rr[0], rr[1], rr[2], rr[3]);
        }
        *(float4*)(out + 4 * i) = r;
    }
}

// Analysis from smem: quad i -> outputs local 4i..4i+3,
// reads in[off + 8i .. off + 8i + 13] (off even: -6 left, 0 right).
__device__ __forceinline__ void afb_q(const float* __restrict__ in,
                                      float* __restrict__ out,
                                      int nq, int off, int tid) {
    for (int i = tid; i < nq; i += NT) {
        const float2* pp = (const float2*)(in + off + 8 * i);
        float2 v0 = pp[0], v1 = pp[1], v2 = pp[2], v3 = pp[3];
        float2 v4 = pp[4], v5 = pp[5], v6 = pp[6];
        float4 r;
        r.x = dot8(v0, v1, v2, v3);
        r.y = dot8(v1, v2, v3, v4);
        r.z = dot8(v2, v3, v4, v5);
        r.w = dot8(v3, v4, v5, v6);
        *(float4*)(out + 4 * i) = r;
    }
}

// Synthesis octave from 7 inputs i0..i6 (in[soff+4u .. +6]).
__device__ __forceinline__ void oct8(float i0, float i1, float i2, float i3,
                                     float i4, float i5, float i6,
                                     float4& a, float4& b) {
    a.x = fmaf(i0, G1, fmaf(i1, G3, fmaf(i2, G5, i3 * G7)));
    a.y = fmaf(i0, G0, fmaf(i1, G2, fmaf(i2, G4, i3 * G6)));
    a.z = fmaf(i1, G1, fmaf(i2, G3, fmaf(i3, G5, i4 * G7)));
    a.w = fmaf(i1, G0, fmaf(i2, G2, fmaf(i3, G4, i4 * G6)));
    b.x = fmaf(i2, G1, fmaf(i3, G3, fmaf(i4, G5, i5 * G7)));
    b.y = fmaf(i2, G0, fmaf(i3, G2, fmaf(i4, G4, i5 * G6)));
    b.z = fmaf(i3, G1, fmaf(i4, G3, fmaf(i5, G5, i6 * G7)));
    b.w = fmaf(i3, G0, fmaf(i4, G2, fmaf(i5, G4, i6 * G6)));
}

// Synthesis: octave u -> outputs local 8u..8u+7, reads in[soff+4u .. +6].
__device__ __forceinline__ void sfb_o(const float* __restrict__ in,
                                      float* __restrict__ out,
                                      int no, int soff, int tid) {
    for (int u = tid; u < no; u += NT) {
        const float2* pp = (const float2*)(in + soff + 4 * u);
        float2 w0 = pp[0], w1 = pp[1], w2 = pp[2], w3 = pp[3];
        float4 a, b;
        oct8(w0.x, w0.y, w1.x, w1.y, w2.x, w2.y, w3.x, a, b);
        *(float4*)(out + 8 * u)     = a;
        *(float4*)(out + 8 * u + 4) = b;
    }
}

__global__ void __launch_bounds__(NT, 4)
wt_kernel(const float* __restrict__ x, float* __restrict__ out) {
    extern __shared__ float sm[];
    float* P1 = sm + 8;
    float* P2 = sm + P1_ALLOC + 8;

    const int tid = threadIdx.x;
    const int row = blockIdx.x >> 1;
    const int h   = blockIdx.x & 1;
    const float* xr = x + (size_t)row * N0;

    // Front zeros (left-half analysis reads down to -6); right lo1 tail pad
    // (= lo1 zero-extension, global 16387..16392).
    if (tid < 8) { P1[tid - 8] = 0.0f; P2[tid - 8] = 0.0f; }
    if (tid < 6) P1[8256 + tid] = 0.0f;

    const int aoff = h ? 0 : -6;   // analysis smem read offset
    const int ob   = h ? 8134 : 0; // stage-1 output global base

    // lo1 -> P1 [0..8255] (+ right-tail zeros at 8253..8255 via guard)
    afb_gq(xr, P1, ob, h ? 0 : 1, h ? 2062 : 2064, tid);
    __syncthreads();

    // lo2 -> P2 [0..4127]; pad [4128..4133] = zero-extension (right needs it)
    afb_q(P1, P2, 1032, aoff, tid);
    if (tid < 6) P2[4128 + tid] = 0.0f;
    __syncthreads();

    // lo3 -> P1 [0..2063]; pad [2064..2069] = zero-extension (right needs it)
    afb_q(P2, P1, 516, aoff, tid);
    if (tid < 6) P1[2064 + tid] = 0.0f;
    __syncthreads();

    // lo4 -> P2 [0..1031]
    afb_q(P1, P2, 258, aoff, tid);
    __syncthreads();

    // t1 -> P1 [0..2063]   (reads lo4 local 0..1034; 1032..1034 stale -> only
    //                       feeds outputs that are never consumed)
    sfb_o(P2, P1, 258, 0, tid);
    __syncthreads();

    // t2 -> P2 [0..4111]
    sfb_o(P1, P2, 514, h ? 2 : 0, tid);
    __syncthreads();

    // t3 -> P1 [0..8199]
    sfb_o(P2, P1, 1025, h ? 2 : 0, tid);
    __syncthreads();

    // Final: octave u -> outputs global goff+8u..+7, fused season = x - trend.
    const int goff = h << 14;
    const int soff = h ? 4 : 0;
    const float* t3 = P1;
    float* season = out + (size_t)row * N0 + goff;
    float* trend  = out + (size_t)HALF + (size_t)row * N0 + goff;
    const float4* x4 = (const float4*)(xr + goff);
    float4* s4p = (float4*)season;
    float4* t4p = (float4*)trend;

    for (int u = tid; u < 2048; u += NT) {
        const float2* pp = (const float2*)(t3 + soff + 4 * u);
        float2 w0 = pp[0], w1 = pp[1], w2 = pp[2], w3 = pp[3];
        float4 a, b;
        oct8(w0.x, w0.y, w1.x, w1.y, w2.x, w2.y, w3.x, a, b);
        float4 xa = x4[2 * u], xb = x4[2 * u + 1];
        t4p[2 * u]     = a;
        t4p[2 * u + 1] = b;
        s4p[2 * u]     = make_float4(xa.x - a.x, xa.y - a.y,
                                     xa.z - a.z, xa.w - a.w);
        s4p[2 * u + 1] = make_float4(xb.x - b.x, xb.y - b.y,
                                     xb.z - b.z, xb.w - b.w);
    }
}

extern "C" void kernel_launch(void* const* d_in, const int* in_sizes, int n_in,
                              void* d_out, int out_size) {
    const float* x = (const float*)d_in[0];
    float* out = (float*)d_out;
    cudaFuncSetAttribute(wt_kernel, cudaFuncAttributeMaxDynamicSharedMemorySize,
                         SMEM_BYTES);
    wt_kernel<<<2 * NROWS, NT, SMEM_BYTES>>>(x, out);
}

// round 12
// speedup vs baseline: 1.0708x; 1.0708x over previous
#include <cuda_runtime.h>

// ---------------------------------------------------------------------------
// WT_series_decomp: 4-level lowpass DWT analysis+synthesis, season = x - trend.
// 2 CTAs per row (halo recompute), 512 thr, 4 CTAs/SM, grid 1024.
// Conflict-free smem: analysis = pair/thread via 3 aligned LDS.128 (16B lane
// stride); synthesis = octave/thread via 2 aligned LDS.128 (soff=0 both halves).
// Right-half bases: lo1:8150 lo2:4078 lo3:2042 lo4:1024 t1:2048 t2:4096 t3:8192
// ---------------------------------------------------------------------------

#define NT      512
#define N0      32768
#define NROWS   512
#define HALF    16777216

#define P1_EXT   8256
#define P2_EXT   4128
#define P1_ALLOC (8 + P1_EXT)               // 8264
#define P2_ALLOC (8 + P2_EXT)               // 4136
#define SMEM_FLOATS (P1_ALLOC + P2_ALLOC)   // 12400
#define SMEM_BYTES  (SMEM_FLOATS * 4)       // 49600 -> 4 CTAs/SM

// DEC_LO
#define G0 (-0.010597401784997278f)
#define G1 ( 0.032883011666982945f)
#define G2 ( 0.030841381835986965f)
#define G3 (-0.18703481171888114f)
#define G4 (-0.02798376941698385f)
#define G5 ( 0.6308807679295904f)
#define G6 ( 0.7148465705525415f)
#define G7 ( 0.23037781330885523f)
// H[k] = DEC_LO[7-k]
#define H0 G7
#define H1 G6
#define H2 G5
#define H3 G4
#define H4 G3
#define H5 G2
#define H6 G1
#define H7 G0

__device__ __forceinline__ float dot8a(const float* w) {
    float s = w[0] * H0;
    s = fmaf(w[1], H1, s);
    s = fmaf(w[2], H2, s);
    s = fmaf(w[3], H3, s);
    s = fmaf(w[4], H4, s);
    s = fmaf(w[5], H5, s);
    s = fmaf(w[6], H6, s);
    s = fmaf(w[7], H7, s);
    return s;
}

#define LOAD12(SRC, f)                                            \
    float4 q0 = (SRC)[0], q1 = (SRC)[1], q2 = (SRC)[2];           \
    float f[12] = {q0.x, q0.y, q0.z, q0.w, q1.x, q1.y, q1.z, q1.w,\
                   q2.x, q2.y, q2.z, q2.w};

// Stage-1 analysis from GLOBAL x. Pair m -> global outputs ob+2m, ob+2m+1;
// window x[2*(ob+2m)-6 .. +3]; aligned fast path (window start ≡ 2 mod 4).
__device__ __forceinline__ void afb_g(const float* __restrict__ x,
                                      float* __restrict__ out,
                                      int ob, int np, int nv,
                                      int m_lo, int m_hi, int tid) {
    const float* xab = x + 2 * ob - 8;
    for (int m = tid; m < np; m += NT) {
        float s0, s1;
        if (m >= m_lo && m < m_hi) {
            const float4* Q = (const float4*)(xab + 4 * m);
            LOAD12(Q, f);
            s0 = dot8a(f + 2);
            s1 = dot8a(f + 4);
        } else {
            int og = ob + 2 * m;
            float v[10];
#pragma unroll
            for (int k = 0; k < 10; ++k) {
                int ix = 2 * og - 6 + k;
                v[k] = (ix >= 0 && ix < N0) ? x[ix] : 0.0f;
            }
            s0 = dot8a(v);
            s1 = dot8a(v + 2);
        }
        int o = 2 * m;
        if (o + 1 < nv)     *(float2*)(out + o) = make_float2(s0, s1);
        else if (o < nv)    out[o] = s0;
    }
}

// Analysis from smem via 3 aligned LDS.128. in_ab = in + (aligned window base
// at m=0). sel = window start - aligned base (literal 0 or 2 at call sites;
// constant-folded after inlining).
__device__ __forceinline__ void afb_s(const float* __restrict__ in_ab,
                                      float* __restrict__ out,
                                      int np, int nv, int sel, int tid) {
    for (int m = tid; m < np; m += NT) {
        const float4* Q = (const float4*)(in_ab + 4 * m);
        LOAD12(Q, f);
        float s0 = dot8a(f + sel);
        float s1 = dot8a(f + sel + 2);
        int o = 2 * m;
        if (o + 1 < nv)     *(float2*)(out + o) = make_float2(s0, s1);
        else if (o < nv)    out[o] = s0;
    }
}

// Synthesis octave from 7 inputs.
__device__ __forceinline__ void oct8(float i0, float i1, float i2, float i3,
                                     float i4, float i5, float i6,
                                     float4& a, float4& b) {
    a.x = fmaf(i0, G1, fmaf(i1, G3, fmaf(i2, G5, i3 * G7)));
    a.y = fmaf(i0, G0, fmaf(i1, G2, fmaf(i2, G4, i3 * G6)));
    a.z = fmaf(i1, G1, fmaf(i2, G3, fmaf(i3, G5, i4 * G7)));
    a.w = fmaf(i1, G0, fmaf(i2, G2, fmaf(i3, G4, i4 * G6)));
    b.x = fmaf(i2, G1, fmaf(i3, G3, fmaf(i4, G5, i5 * G7)));
    b.y = fmaf(i2, G0, fmaf(i3, G2, fmaf(i4, G4, i5 * G6)));
    b.z = fmaf(i3, G1, fmaf(i4, G3, fmaf(i5, G5, i6 * G7)));
    b.w = fmaf(i3, G0, fmaf(i4, G2, fmaf(i5, G4, i6 * G6)));
}

// Synthesis: octave u -> out[8u..8u+7] from in[4u..4u+6] (2 aligned LDS.128).
__device__ __forceinline__ void sfb8(const float* __restrict__ in,
                                     float* __restrict__ out,
                                     int nu, int tid) {
    for (int u = tid; u < nu; u += NT) {
        const float4* Q = (const float4*)(in + 4 * u);
        float4 q0 = Q[0], q1 = Q[1];
        float4 a, b;
        oct8(q0.x, q0.y, q0.z, q0.w, q1.x, q1.y, q1.z, a, b);
        *(float4*)(out + 8 * u)     = a;
        *(float4*)(out + 8 * u + 4) = b;
    }
}

__global__ void __launch_bounds__(NT, 4)
wt_kernel(const float* __restrict__ x, float* __restrict__ out) {
    extern __shared__ float sm[];
    float* P1 = sm + 8;                 // 16B aligned
    float* P2 = sm + P1_ALLOC + 8;      // 16B aligned

    const int tid = threadIdx.x;
    const int row = blockIdx.x >> 1;
    const int h   = blockIdx.x & 1;
    const float* xr = x + (size_t)row * N0;

    // Front zero margins (left-half aligned reads reach -8)
    if (tid < 8) { P1[tid - 8] = 0.0f; P2[tid - 8] = 0.0f; }

    if (h == 0) {
        // ---------------- left half (all bases 0) ----------------
        afb_g(xr, P1, 0, 4128, 8256, 2, 4128, tid);          // lo1 -> P1[0..8255]
        __syncthreads();
        afb_s(P1 - 8, P2, 2064, 4128, 2, tid);               // lo2 -> P2[0..4127]
        __syncthreads();
        afb_s(P2 - 8, P1, 1032, 2064, 2, tid);               // lo3 -> P1[0..2063]
        __syncthreads();
        afb_s(P1 - 8, P2, 515, 1030, 2, tid);                // lo4 -> P2[0..1029]
        if (tid < 6) P2[1030 + tid] = 0.0f;                  // dead-lane pad
        __syncthreads();
    } else {
        // ---------------- right half ----------------
        // lo1 base 8150 -> P1 local [0..8236]; zeros 8237.. = zero-extension
        afb_g(xr, P1, 8150, 4119, 8237, 0, 4117, tid);
        if (tid < 11) P1[8237 + tid] = 0.0f;
        __syncthreads();
        // lo2 base 4078 -> P2 [0..4118]; 4119.. = zero-extension (lo2 len 8197)
        afb_s(P1, P2, 2060, 4119, 0, tid);
        if (tid < 9) P2[4119 + tid] = 0.0f;
        __syncthreads();
        // lo3 base 2042 -> P1 [0..2059]; 2060.. = zero-extension (lo3 len 4102)
        afb_s(P2, P1, 1030, 2060, 0, tid);
        if (tid < 8) P1[2060 + tid] = 0.0f;
        __syncthreads();
        // lo4 base 1024 -> P2 [0..1029]; 1030.. = zero-extension (lo4 len 2054)
        afb_s(P1, P2, 515, 1030, 0, tid);
        if (tid < 6) P2[1030 + tid] = 0.0f;
        __syncthreads();
    }

    // ---------------- synthesis (identical both halves, soff = 0) ----------
    sfb8(P2, P1, 258, tid);  __syncthreads();   // t1 -> P1[0..2063]
    sfb8(P1, P2, 514, tid);  __syncthreads();   // t2 -> P2[0..4111]
    sfb8(P2, P1, 1025, tid); __syncthreads();   // t3 -> P1[0..8199]

    // Final: octave u -> out global goff+8u..+7, fused season = x - trend.
    const int goff = h << 14;
    const float* t3 = P1;
    float* season = out + (size_t)row * N0 + goff;
    float* trend  = out + (size_t)HALF + (size_t)row * N0 + goff;
    const float4* x4 = (const float4*)(xr + goff);
    float4* s4p = (float4*)season;
    float4* t4p = (float4*)trend;

    for (int u = tid; u < 2048; u += NT) {
        const float4* Q = (const float4*)(t3 + 4 * u);
        float4 q0 = Q[0], q1 = Q[1];
        float4 a, b;
        oct8(q0.x, q0.y, q0.z, q0.w, q1.x, q1.y, q1.z, a, b);
        float4 xa = x4[2 * u], xb = x4[2 * u + 1];
        t4p[2 * u]     = a;
        t4p[2 * u + 1] = b;
        s4p[2 * u]     = make_float4(xa.x - a.x, xa.y - a.y,
                                     xa.z - a.z, xa.w - a.w);
        s4p[2 * u + 1] = make_float4(xb.x - b.x, xb.y - b.y,
                                     xb.z - b.z, xb.w - b.w);
    }
}

extern "C" void kernel_launch(void* const* d_in, const int* in_sizes, int n_in,
                              void* d_out, int out_size) {
    const float* x = (const float*)d_in[0];
    float* out = (float*)d_out;
    cudaFuncSetAttribute(wt_kernel, cudaFuncAttributeMaxDynamicSharedMemorySize,
                         SMEM_BYTES);
    wt_kernel<<<2 * NROWS, NT, SMEM_BYTES>>>(x, out);
}

// round 13
// speedup vs baseline: 1.0713x; 1.0005x over previous
#include <cuda_runtime.h>

// ---------------------------------------------------------------------------
// WT_series_decomp: 4-level lowpass DWT analysis+synthesis, season = x - trend.
// 2 CTAs per row (halo recompute), 512 thr, 4 CTAs/SM, grid 1024.
// Conflict-free smem: analysis = pair/thread via 3 aligned LDS.128 (16B lane
// stride); synthesis = octave/thread via 2 aligned LDS.128 (soff=0 both halves).
// Window selection hardcoded (afb_s0 / afb_s2) - no dynamic local indexing.
// Right-half bases: lo1:8150 lo2:4078 lo3:2042 lo4:1024 t1:2048 t2:4096 t3:8192
// ---------------------------------------------------------------------------

#define NT      512
#define N0      32768
#define NROWS   512
#define HALF    16777216

#define P1_EXT   8256
#define P2_EXT   4128
#define P1_ALLOC (8 + P1_EXT)               // 8264
#define P2_ALLOC (8 + P2_EXT)               // 4136
#define SMEM_FLOATS (P1_ALLOC + P2_ALLOC)   // 12400
#define SMEM_BYTES  (SMEM_FLOATS * 4)       // 49600 -> 4 CTAs/SM

// DEC_LO
#define G0 (-0.010597401784997278f)
#define G1 ( 0.032883011666982945f)
#define G2 ( 0.030841381835986965f)
#define G3 (-0.18703481171888114f)
#define G4 (-0.02798376941698385f)
#define G5 ( 0.6308807679295904f)
#define G6 ( 0.7148465705525415f)
#define G7 ( 0.23037781330885523f)
// H[k] = DEC_LO[7-k]
#define H0 G7
#define H1 G6
#define H2 G5
#define H3 G4
#define H4 G3
#define H5 G2
#define H6 G1
#define H7 G0

__device__ __forceinline__ float dot8s(float w0, float w1, float w2, float w3,
                                       float w4, float w5, float w6, float w7) {
    float s = w0 * H0;
    s = fmaf(w1, H1, s);
    s = fmaf(w2, H2, s);
    s = fmaf(w3, H3, s);
    s = fmaf(w4, H4, s);
    s = fmaf(w5, H5, s);
    s = fmaf(w6, H6, s);
    s = fmaf(w7, H7, s);
    return s;
}

// Stage-1 analysis from GLOBAL x. Pair m -> global outputs ob+2m, ob+2m+1;
// window x[2*(ob+2m)-6 .. +3]; aligned fast path (window = f[2..11] of the
// 12-float aligned block).
__device__ __forceinline__ void afb_g(const float* __restrict__ x,
                                      float* __restrict__ out,
                                      int ob, int np, int nv,
                                      int m_lo, int m_hi, int tid) {
    const float* xab = x + 2 * ob - 8;
    for (int m = tid; m < np; m += NT) {
        float s0, s1;
        if (m >= m_lo && m < m_hi) {
            const float4* Q = (const float4*)(xab + 4 * m);
            float4 q0 = Q[0], q1 = Q[1], q2 = Q[2];
            s0 = dot8s(q0.z, q0.w, q1.x, q1.y, q1.z, q1.w, q2.x, q2.y);
            s1 = dot8s(q1.x, q1.y, q1.z, q1.w, q2.x, q2.y, q2.z, q2.w);
        } else {
            int og = ob + 2 * m;
            float v[10];
#pragma unroll
            for (int k = 0; k < 10; ++k) {
                int ix = 2 * og - 6 + k;
                v[k] = (ix >= 0 && ix < N0) ? x[ix] : 0.0f;
            }
            s0 = dot8s(v[0], v[1], v[2], v[3], v[4], v[5], v[6], v[7]);
            s1 = dot8s(v[2], v[3], v[4], v[5], v[6], v[7], v[8], v[9]);
        }
        int o = 2 * m;
        if (o + 1 < nv)     *(float2*)(out + o) = make_float2(s0, s1);
        else if (o < nv)    out[o] = s0;
    }
}

// Analysis from smem, window = f[0..9] of the aligned 12-float block.
__device__ __forceinline__ void afb_s0(const float* __restrict__ in_ab,
                                       float* __restrict__ out,
                                       int np, int nv, int tid) {
    for (int m = tid; m < np; m += NT) {
        const float4* Q = (const float4*)(in_ab + 4 * m);
        float4 q0 = Q[0], q1 = Q[1], q2 = Q[2];
        float s0 = dot8s(q0.x, q0.y, q0.z, q0.w, q1.x, q1.y, q1.z, q1.w);
        float s1 = dot8s(q0.z, q0.w, q1.x, q1.y, q1.z, q1.w, q2.x, q2.y);
        int o = 2 * m;
        if (o + 1 < nv)     *(float2*)(out + o) = make_float2(s0, s1);
        else if (o < nv)    out[o] = s0;
    }
}

// Analysis from smem, window = f[2..11] of the aligned 12-float block.
__device__ __forceinline__ void afb_s2(const float* __restrict__ in_ab,
                                       float* __restrict__ out,
                                       int np, int nv, int tid) {
    for (int m = tid; m < np; m += NT) {
        const float4* Q = (const float4*)(in_ab + 4 * m);
        float4 q0 = Q[0], q1 = Q[1], q2 = Q[2];
        float s0 = dot8s(q0.z, q0.w, q1.x, q1.y, q1.z, q1.w, q2.x, q2.y);
        float s1 = dot8s(q1.x, q1.y, q1.z, q1.w, q2.x, q2.y, q2.z, q2.w);
        int o = 2 * m;
        if (o + 1 < nv)     *(float2*)(out + o) = make_float2(s0, s1);
        else if (o < nv)    out[o] = s0;
    }
}

// Synthesis octave from 7 inputs.
__device__ __forceinline__ void oct8(float i0, float i1, float i2, float i3,
                                     float i4, float i5, float i6,
                                     float4& a, float4& b) {
    a.x = fmaf(i0, G1, fmaf(i1, G3, fmaf(i2, G5, i3 * G7)));
    a.y = fmaf(i0, G0, fmaf(i1, G2, fmaf(i2, G4, i3 * G6)));
    a.z = fmaf(i1, G1, fmaf(i2, G3, fmaf(i3, G5, i4 * G7)));
    a.w = fmaf(i1, G0, fmaf(i2, G2, fmaf(i3, G4, i4 * G6)));
    b.x = fmaf(i2, G1, fmaf(i3, G3, fmaf(i4, G5, i5 * G7)));
    b.y = fmaf(i2, G0, fmaf(i3, G2, fmaf(i4, G4, i5 * G6)));
    b.z = fmaf(i3, G1, fmaf(i4, G3, fmaf(i5, G5, i6 * G7)));
    b.w = fmaf(i3, G0, fmaf(i4, G2, fmaf(i5, G4, i6 * G6)));
}

// Synthesis: octave u -> out[8u..8u+7] from in[4u..4u+6] (2 aligned LDS.128).
__device__ __forceinline__ void sfb8(const float* __restrict__ in,
                                     float* __restrict__ out,
                                     int nu, int tid) {
    for (int u = tid; u < nu; u += NT) {
        const float4* Q = (const float4*)(in + 4 * u);
        float4 q0 = Q[0], q1 = Q[1];
        float4 a, b;
        oct8(q0.x, q0.y, q0.z, q0.w, q1.x, q1.y, q1.z, a, b);
        *(float4*)(out + 8 * u)     = a;
        *(float4*)(out + 8 * u + 4) = b;
    }
}

__global__ void __launch_bounds__(NT, 4)
wt_kernel(const float* __restrict__ x, float* __restrict__ out) {
    extern __shared__ float sm[];
    float* P1 = sm + 8;                 // 16B aligned
    float* P2 = sm + P1_ALLOC + 8;      // 16B aligned

    const int tid = threadIdx.x;
    const int row = blockIdx.x >> 1;
    const int h   = blockIdx.x & 1;
    const float* xr = x + (size_t)row * N0;

    // Front zero margins (left-half aligned reads reach -8)
    if (tid < 8) { P1[tid - 8] = 0.0f; P2[tid - 8] = 0.0f; }

    if (h == 0) {
        // ---------------- left half (all bases 0) ----------------
        afb_g(xr, P1, 0, 4128, 8256, 2, 4128, tid);        // lo1 -> P1[0..8255]
        __syncthreads();
        afb_s2(P1 - 8, P2, 2064, 4128, tid);               // lo2 -> P2[0..4127]
        __syncthreads();
        afb_s2(P2 - 8, P1, 1032, 2064, tid);               // lo3 -> P1[0..2063]
        __syncthreads();
        afb_s2(P1 - 8, P2, 515, 1030, tid);                // lo4 -> P2[0..1029]
        if (tid < 6) P2[1030 + tid] = 0.0f;                // dead-lane pad
        __syncthreads();
    } else {
        // ---------------- right half ----------------
        // lo1 base 8150 -> P1 local [0..8236]; zeros 8237.. = zero-extension
        afb_g(xr, P1, 8150, 4119, 8237, 0, 4117, tid);
        if (tid < 11) P1[8237 + tid] = 0.0f;
        __syncthreads();
        // lo2 base 4078 -> P2 [0..4118]; 4119.. = zero-extension (lo2 len 8197)
        afb_s0(P1, P2, 2060, 4119, tid);
        if (tid < 9) P2[4119 + tid] = 0.0f;
        __syncthreads();
        // lo3 base 2042 -> P1 [0..2059]; 2060.. = zero-extension (lo3 len 4102)
        afb_s0(P2, P1, 1030, 2060, tid);
        if (tid < 8) P1[2060 + tid] = 0.0f;
        __syncthreads();
        // lo4 base 1024 -> P2 [0..1029]; 1030.. = zero-extension (lo4 len 2054)
        afb_s0(P1, P2, 515, 1030, tid);
        if (tid < 6) P2[1030 + tid] = 0.0f;
        __syncthreads();
    }

    // ---------------- synthesis (identical both halves, soff = 0) ----------
    sfb8(P2, P1, 258, tid);  __syncthreads();   // t1 -> P1[0..2063]
    sfb8(P1, P2, 514, tid);  __syncthreads();   // t2 -> P2[0..4111]
    sfb8(P2, P1, 1025, tid); __syncthreads();   // t3 -> P1[0..8199]

    // Final: octave u -> out global goff+8u..+7, fused season = x - trend.
    const int goff = h << 14;
    const float* t3 = P1;
    float* season = out + (size_t)row * N0 + goff;
    float* trend  = out + (size_t)HALF + (size_t)row * N0 + goff;
    const float4* x4 = (const float4*)(xr + goff);
    float4* s4p = (float4*)season;
    float4* t4p = (float4*)trend;

    for (int u = tid; u < 2048; u += NT) {
        const float4* Q = (const float4*)(t3 + 4 * u);
        float4 q0 = Q[0], q1 = Q[1];
        float4 a, b;
        oct8(q0.x, q0.y, q0.z, q0.w, q1.x, q1.y, q1.z, a, b);
        float4 xa = x4[2 * u], xb = x4[2 * u + 1];
        t4p[2 * u]     = a;
        t4p[2 * u + 1] = b;
        s4p[2 * u]     = make_float4(xa.x - a.x, xa.y - a.y,
                                     xa.z - a.z, xa.w - a.w);
        s4p[2 * u + 1] = make_float4(xb.x - b.x, xb.y - b.y,
                                     xb.z - b.z, xb.w - b.w);
    }
}

extern "C" void kernel_launch(void* const* d_in, const int* in_sizes, int n_in,
                              void* d_out, int out_size) {
    const float* x = (const float*)d_in[0];
    float* out = (float*)d_out;
    cudaFuncSetAttribute(wt_kernel, cudaFuncAttributeMaxDynamicSharedMemorySize,
                         SMEM_BYTES);
    wt_kernel<<<2 * NROWS, NT, SMEM_BYTES>>>(x, out);
}